// round 7
// baseline (speedup 1.0000x reference)
#include <cuda_runtime.h>

#define NN   100000
#define NE   800000
#define FIN  128
#define HID  512
#define NCLS 40
#define BN_EPS 1e-5f

// ---------------- scratch (static device arrays: allocation-free) ----------------
__device__ __align__(16) float g_h  [(size_t)NN * HID];   // GEMM output (h = x @ W)
__device__ __align__(16) float g_agg[(size_t)NN * HID];   // aggregation / y / x3
__device__ __align__(16) float g_h3 [(size_t)NN * NCLS];
__device__ __align__(16) float g_ag3[(size_t)NN * NCLS];
__device__ int   g_src[NE];
__device__ int   g_dst[NE];
__device__ int   g_is64;
__device__ int   g_deg[NN];
__device__ float g_dinv[NN];
__device__ float g_stats[2 * HID];   // per-column sum, sumsq
__device__ float g_scale[HID];
__device__ float g_shift[HID];

// ---------------- edge-index dtype probe + conversion ----------------
// If the buffer is int64 (little-endian, values < 2^31), every odd 32-bit word
// of the first 256 pairs is zero. For int32 data those words are random node
// indices, so at least one is nonzero with overwhelming probability.
__global__ void k_detect(const int* __restrict__ raw) {
    __shared__ int nz;
    if (threadIdx.x == 0) nz = 0;
    __syncthreads();
    if (raw[threadIdx.x * 2 + 1] != 0) atomicAdd(&nz, 1);
    __syncthreads();
    if (threadIdx.x == 0) g_is64 = (nz == 0) ? 1 : 0;
}

__global__ void k_convert(const int* __restrict__ raw) {
    int i = blockIdx.x * blockDim.x + threadIdx.x;
    if (i >= NE) return;
    int s, d;
    if (g_is64) {
        s = raw[2 * i];
        d = raw[2 * (NE + i)];
    } else {
        s = raw[i];
        d = raw[NE + i];
    }
    // clamp defensively (never triggers on valid input)
    if ((unsigned)s >= NN) s = 0;
    if ((unsigned)d >= NN) d = 0;
    g_src[i] = s;
    g_dst[i] = d;
}

// ---------------- utility kernels ----------------
__global__ void k_zero_f4(float* p, long n) {
    long i  = ((long)blockIdx.x * blockDim.x + threadIdx.x) * 4;
    long st = (long)gridDim.x * blockDim.x * 4;
    float4 z = make_float4(0.f, 0.f, 0.f, 0.f);
    for (; i < n; i += st) *reinterpret_cast<float4*>(p + i) = z;
}

__global__ void k_zero_i(int* p, int n) {
    int i = blockIdx.x * blockDim.x + threadIdx.x;
    if (i < n) p[i] = 0;
}

__global__ void k_deg(int E) {
    int i = blockIdx.x * blockDim.x + threadIdx.x;
    if (i < E) atomicAdd(&g_deg[g_dst[i]], 1);
}

__global__ void k_dinv(int n) {
    int i = blockIdx.x * blockDim.x + threadIdx.x;
    if (i < n) g_dinv[i] = rsqrtf((float)g_deg[i] + 1.0f);
}

// ---------------- tiled fp32 GEMM: C[M,N] = A[M,K] @ W[K,N] (row-major) ----------
#define BM 64
#define BN 64
#define BK 16
__global__ void k_gemm(const float* __restrict__ A, const float* __restrict__ W,
                       float* __restrict__ C, int M, int N, int K) {
    __shared__ float As[BK][BM + 4];
    __shared__ float Bs[BK][BN + 4];
    const int tid = threadIdx.x;
    const int tx = tid & 15;          // 0..15 -> N
    const int ty = tid >> 4;          // 0..15 -> M
    const int row0 = blockIdx.y * BM + ty * 4;
    const int col0 = blockIdx.x * BN + tx * 4;

    float acc[4][4];
#pragma unroll
    for (int i = 0; i < 4; i++)
#pragma unroll
        for (int j = 0; j < 4; j++) acc[i][j] = 0.f;

    for (int k0 = 0; k0 < K; k0 += BK) {
#pragma unroll
        for (int i = tid; i < BM * BK; i += 256) {
            int r = i >> 4, c = i & 15;
            int gr = blockIdx.y * BM + r;
            As[c][r] = (gr < M) ? A[(size_t)gr * K + (k0 + c)] : 0.f;
        }
#pragma unroll
        for (int i = tid; i < BK * BN; i += 256) {
            int r = i >> 6, c = i & 63;
            int gc = blockIdx.x * BN + c;
            Bs[r][c] = (gc < N) ? W[(size_t)(k0 + r) * N + gc] : 0.f;
        }
        __syncthreads();
#pragma unroll
        for (int k = 0; k < BK; k++) {
            float4 av = *reinterpret_cast<const float4*>(&As[k][ty * 4]);
            float4 bv = *reinterpret_cast<const float4*>(&Bs[k][tx * 4]);
            float a[4] = {av.x, av.y, av.z, av.w};
            float b[4] = {bv.x, bv.y, bv.z, bv.w};
#pragma unroll
            for (int i = 0; i < 4; i++)
#pragma unroll
                for (int j = 0; j < 4; j++) acc[i][j] += a[i] * b[j];
        }
        __syncthreads();
    }
#pragma unroll
    for (int i = 0; i < 4; i++) {
        int r = row0 + i;
        if (r >= M) continue;
#pragma unroll
        for (int j = 0; j < 4; j++) {
            int c = col0 + j;
            if (c < N) C[(size_t)r * N + c] = acc[i][j];
        }
    }
}

// ---------------- edge scatter: agg[dst] += h[src] * dinv[src]*dinv[dst] --------
// one warp per edge, float4 vectorized atomic reductions
__global__ void k_scatter(const float* __restrict__ h, float* agg, int E, int F) {
    int w = (blockIdx.x * blockDim.x + threadIdx.x) >> 5;
    int lane = threadIdx.x & 31;
    if (w >= E) return;
    int s = g_src[w];
    int d = g_dst[w];
    float norm = g_dinv[s] * g_dinv[d];
    const float4* hp = reinterpret_cast<const float4*>(h + (size_t)s * F);
    float* ap = agg + (size_t)d * F;
    int vecs = F >> 2;
    for (int v = lane; v < vecs; v += 32) {
        float4 x = hp[v];
        x.x *= norm; x.y *= norm; x.z *= norm; x.w *= norm;
        asm volatile("red.global.add.v4.f32 [%0], {%1,%2,%3,%4};"
                     :: "l"(ap + (size_t)v * 4),
                        "f"(x.x), "f"(x.y), "f"(x.z), "f"(x.w)
                     : "memory");
    }
}

// ---- combine self-loop + bias into y (in place in agg) and accumulate BN stats --
__global__ void k_combine_stats(float* agg, const float* __restrict__ h,
                                const float* __restrict__ bias, int Nn, int F) {
    int c0 = threadIdx.x;
    int c1 = threadIdx.x + 256;
    bool a0 = c0 < F, a1 = c1 < F;
    float b0 = a0 ? bias[c0] : 0.f;
    float b1 = a1 ? bias[c1] : 0.f;
    float s0 = 0.f, q0 = 0.f, s1 = 0.f, q1 = 0.f;
    for (int r = blockIdx.x; r < Nn; r += gridDim.x) {
        float di = g_dinv[r];
        float d2 = di * di;
        size_t base = (size_t)r * F;
        if (a0) {
            float y = agg[base + c0] + h[base + c0] * d2 + b0;
            agg[base + c0] = y; s0 += y; q0 += y * y;
        }
        if (a1) {
            float y = agg[base + c1] + h[base + c1] * d2 + b1;
            agg[base + c1] = y; s1 += y; q1 += y * y;
        }
    }
    if (a0) { atomicAdd(&g_stats[c0], s0); atomicAdd(&g_stats[F + c0], q0); }
    if (a1) { atomicAdd(&g_stats[c1], s1); atomicAdd(&g_stats[F + c1], q1); }
}

__global__ void k_finalize(const float* __restrict__ g, const float* __restrict__ be,
                           int F, float invN) {
    int c = blockIdx.x * blockDim.x + threadIdx.x;
    if (c >= F) return;
    float mean = g_stats[c] * invN;
    float var  = g_stats[F + c] * invN - mean * mean;
    float sc = g[c] * rsqrtf(var + BN_EPS);
    g_scale[c] = sc;
    g_shift[c] = be[c] - mean * sc;
}

__global__ void k_apply(const float* __restrict__ y, float* __restrict__ o,
                        long n, int F, int relu) {
    long i  = ((long)blockIdx.x * blockDim.x + threadIdx.x) * 4;
    long st = (long)gridDim.x * blockDim.x * 4;
    for (; i < n; i += st) {
        float4 v = *reinterpret_cast<const float4*>(y + i);
        int c = (int)(i % F);
        v.x = v.x * g_scale[c]     + g_shift[c];
        v.y = v.y * g_scale[c + 1] + g_shift[c + 1];
        v.z = v.z * g_scale[c + 2] + g_shift[c + 2];
        v.w = v.w * g_scale[c + 3] + g_shift[c + 3];
        if (relu) {
            v.x = fmaxf(v.x, 0.f); v.y = fmaxf(v.y, 0.f);
            v.z = fmaxf(v.z, 0.f); v.w = fmaxf(v.w, 0.f);
        }
        *reinterpret_cast<float4*>(o + i) = v;
    }
}

// ---------------- host launch -----------------------------------------------
extern "C" void kernel_launch(void* const* d_in, const int* in_sizes, int n_in,
                              void* d_out, int out_size) {
    const float* x  = (const float*)d_in[0];
    const int*   ei = (const int*)d_in[1];   // int32 or int64 words; probed on device
    const float *W1 = (const float*)d_in[2],  *b1 = (const float*)d_in[3];
    const float *g1 = (const float*)d_in[4],  *be1 = (const float*)d_in[5];
    const float *W2 = (const float*)d_in[6],  *b2 = (const float*)d_in[7];
    const float *g2 = (const float*)d_in[8],  *be2 = (const float*)d_in[9];
    const float *W3 = (const float*)d_in[10], *b3 = (const float*)d_in[11];
    const float *g3 = (const float*)d_in[12], *be3 = (const float*)d_in[13];

    float* out = (float*)d_out;                 // [NN, NCLS]
    float* x6  = out + (size_t)NN * NCLS;       // [NN, HID]

    void* p;
    cudaGetSymbolAddress(&p, g_h);    float* hbuf  = (float*)p;
    cudaGetSymbolAddress(&p, g_agg);  float* agg   = (float*)p;
    cudaGetSymbolAddress(&p, g_h3);   float* h3    = (float*)p;
    cudaGetSymbolAddress(&p, g_ag3);  float* agg3  = (float*)p;
    cudaGetSymbolAddress(&p, g_deg);  int*   deg   = (int*)p;
    cudaGetSymbolAddress(&p, g_stats);float* stats = (float*)p;

    const long NH = (long)NN * HID;
    const long NC = (long)NN * NCLS;
    const int  GZ = 4096;
    const int  SCAT_BLOCKS = (NE * 32) / 256;   // exactly 100000
    const float invN = 1.0f / (float)NN;

    // decode edge index (dtype-robust), degrees -> dinv
    k_detect <<<1, 256>>>(ei);
    k_convert<<<(NE + 255) / 256, 256>>>(ei);
    k_zero_i<<<(NN + 255) / 256, 256>>>(deg, NN);
    k_deg  <<<(NE + 255) / 256, 256>>>(NE);
    k_dinv <<<(NN + 255) / 256, 256>>>(NN);

    dim3 gb1(HID / BN, (NN + BM - 1) / BM);
    dim3 gb3(1,        (NN + BM - 1) / BM);

    // -------- Layer 1 --------
    k_gemm<<<gb1, 256>>>(x, W1, hbuf, NN, HID, FIN);
    k_zero_f4<<<GZ, 256>>>(agg, NH);
    k_scatter<<<SCAT_BLOCKS, 256>>>(hbuf, agg, NE, HID);
    k_zero_f4<<<1, 256>>>(stats, 2 * HID);
    k_combine_stats<<<2048, 256>>>(agg, hbuf, b1, NN, HID);
    k_finalize<<<2, 256>>>(g1, be1, HID, invN);
    k_apply<<<GZ, 256>>>(agg, agg, NH, HID, 1);           // x3 (in place)

    // -------- Layer 2 --------
    k_gemm<<<gb1, 256>>>(agg, W2, hbuf, NN, HID, HID);
    k_zero_f4<<<GZ, 256>>>(agg, NH);
    k_scatter<<<SCAT_BLOCKS, 256>>>(hbuf, agg, NE, HID);
    k_zero_f4<<<1, 256>>>(stats, 2 * HID);
    k_combine_stats<<<2048, 256>>>(agg, hbuf, b2, NN, HID);
    k_finalize<<<2, 256>>>(g2, be2, HID, invN);
    k_apply<<<GZ, 256>>>(agg, x6, NH, HID, 1);            // x6 -> output

    // -------- Layer 3 --------
    k_gemm<<<gb3, 256>>>(x6, W3, h3, NN, NCLS, HID);
    k_zero_f4<<<GZ, 256>>>(agg3, NC);
    k_scatter<<<SCAT_BLOCKS, 256>>>(h3, agg3, NE, NCLS);
    k_zero_f4<<<1, 256>>>(stats, 2 * HID);
    k_combine_stats<<<2048, 256>>>(agg3, h3, b3, NN, NCLS);
    k_finalize<<<1, 64>>>(g3, be3, NCLS, invN);
    k_apply<<<GZ, 256>>>(agg3, out, NC, NCLS, 0);         // out -> output
}

// round 12
// speedup vs baseline: 2.2903x; 2.2903x over previous
#include <cuda_runtime.h>
#include <cuda_bf16.h>

#define NN   100000
#define NE   800000
#define FIN  128
#define HID  512
#define NCLS 40
#define BN_EPS 1e-5f

// ---------------- scratch ----------------
__device__ __align__(16) float g_bufA[(size_t)NN * HID];   // y1 / y2
__device__ __align__(16) float g_bufB[(size_t)NN * HID];   // px / p2
__device__ __align__(16) float g_h3 [(size_t)NN * NCLS];
__device__ __align__(16) float g_ag3[(size_t)NN * NCLS];
__device__ int   g_src[NE];
__device__ int   g_dst[NE];
__device__ int   g_is64;
__device__ int   g_deg[NN];
__device__ float g_dinv[NN];
__device__ float g_stats[2 * HID];
__device__ float g_scale[HID];
__device__ float g_shift[HID];

// ---------------- edge-index dtype probe + conversion ----------------
__global__ void k_detect(const int* __restrict__ raw) {
    __shared__ int nz;
    if (threadIdx.x == 0) nz = 0;
    __syncthreads();
    if (raw[threadIdx.x * 2 + 1] != 0) atomicAdd(&nz, 1);
    __syncthreads();
    if (threadIdx.x == 0) g_is64 = (nz == 0) ? 1 : 0;
}

__global__ void k_convert(const int* __restrict__ raw) {
    int i = blockIdx.x * blockDim.x + threadIdx.x;
    if (i >= NE) return;
    int s, d;
    if (g_is64) { s = raw[2 * i]; d = raw[2 * (NE + i)]; }
    else        { s = raw[i];     d = raw[NE + i]; }
    if ((unsigned)s >= NN) s = 0;
    if ((unsigned)d >= NN) d = 0;
    g_src[i] = s; g_dst[i] = d;
}

// ---------------- utility kernels ----------------
__global__ void k_zero_f4(float* p, long n) {
    long i  = ((long)blockIdx.x * blockDim.x + threadIdx.x) * 4;
    long st = (long)gridDim.x * blockDim.x * 4;
    float4 z = make_float4(0.f, 0.f, 0.f, 0.f);
    for (; i < n; i += st) *reinterpret_cast<float4*>(p + i) = z;
}

__global__ void k_zero_i(int* p, int n) {
    int i = blockIdx.x * blockDim.x + threadIdx.x;
    if (i < n) p[i] = 0;
}

__global__ void k_deg(int E) {
    int i = blockIdx.x * blockDim.x + threadIdx.x;
    if (i < E) atomicAdd(&g_deg[g_dst[i]], 1);
}

__global__ void k_dinv(int n) {
    int i = blockIdx.x * blockDim.x + threadIdx.x;
    if (i < n) g_dinv[i] = rsqrtf((float)g_deg[i] + 1.0f);
}

// ---------------- bf16 split helpers ----------------
__device__ __forceinline__ void split_bf16(float x, __nv_bfloat16& h, __nv_bfloat16& l) {
    h = __float2bfloat16(x);
    l = __float2bfloat16(x - __bfloat162float(h));
}

__device__ __forceinline__ void ldsm_x4(unsigned* r, const void* p) {
    unsigned a = (unsigned)__cvta_generic_to_shared(p);
    asm volatile("ldmatrix.sync.aligned.m8n8.x4.shared.b16 {%0,%1,%2,%3}, [%4];"
                 : "=r"(r[0]), "=r"(r[1]), "=r"(r[2]), "=r"(r[3]) : "r"(a));
}
__device__ __forceinline__ void ldsm_x2t(unsigned* r, const void* p) {
    unsigned a = (unsigned)__cvta_generic_to_shared(p);
    asm volatile("ldmatrix.sync.aligned.m8n8.x2.trans.shared.b16 {%0,%1}, [%2];"
                 : "=r"(r[0]), "=r"(r[1]) : "r"(a));
}
__device__ __forceinline__ void mma_bf16(float* c, const unsigned* a, const unsigned* b) {
    asm volatile("mma.sync.aligned.m16n8k16.row.col.f32.bf16.bf16.f32 "
                 "{%0,%1,%2,%3}, {%4,%5,%6,%7}, {%8,%9}, {%0,%1,%2,%3};"
                 : "+f"(c[0]), "+f"(c[1]), "+f"(c[2]), "+f"(c[3])
                 : "r"(a[0]), "r"(a[1]), "r"(a[2]), "r"(a[3]),
                   "r"(b[0]), "r"(b[1]));
}

// ---------------- tensor-core GEMM (bf16 3-term split), C = A@W (+bias) ----------
// block tile 128x128, BK=32, 8 warps (2x4), warp tile 64x32
#define TBM 128
#define TBN 128
#define TBK 32
#define SAK 40    // As row stride (bf16 elems), padded
#define SBN 136   // Bs row stride (bf16 elems), padded

__global__ __launch_bounds__(256, 1) void k_gemm_tc(
    const float* __restrict__ A, const float* __restrict__ W,
    const float* __restrict__ bias, float* __restrict__ C,
    int M, int N, int K, int do_stats)
{
    __shared__ __nv_bfloat16 As_hi[TBM * SAK], As_lo[TBM * SAK];
    __shared__ __nv_bfloat16 Bs_hi[TBK * SBN], Bs_lo[TBK * SBN];

    const int tid  = threadIdx.x;
    const int warp = tid >> 5, lane = tid & 31;
    const int wm = warp >> 2, wn = warp & 3;          // 2 x 4 warp grid
    const int rowBase = blockIdx.y * TBM;
    const int colBase = blockIdx.x * TBN;

    float acc[4][4][4];
#pragma unroll
    for (int i = 0; i < 4; i++)
#pragma unroll
        for (int j = 0; j < 4; j++)
#pragma unroll
            for (int k = 0; k < 4; k++) acc[i][j][k] = 0.f;

    const float4 z4 = make_float4(0.f, 0.f, 0.f, 0.f);

    for (int k0 = 0; k0 < K; k0 += TBK) {
        // ---- load A tile [128 x 32] fp32 -> split bf16 ----
#pragma unroll
        for (int i = 0; i < 4; i++) {
            int f  = tid + i * 256;          // 0..1023
            int r  = f >> 3;                 // 0..127
            int c4 = (f & 7) << 2;           // 0,4,..,28
            int gr = rowBase + r;
            float4 v = (gr < M) ? *reinterpret_cast<const float4*>(A + (size_t)gr * K + k0 + c4) : z4;
            __nv_bfloat16 h, l;
            int o = r * SAK + c4;
            split_bf16(v.x, h, l); As_hi[o + 0] = h; As_lo[o + 0] = l;
            split_bf16(v.y, h, l); As_hi[o + 1] = h; As_lo[o + 1] = l;
            split_bf16(v.z, h, l); As_hi[o + 2] = h; As_lo[o + 2] = l;
            split_bf16(v.w, h, l); As_hi[o + 3] = h; As_lo[o + 3] = l;
        }
        // ---- load B tile [32 x 128] fp32 -> split bf16 ----
#pragma unroll
        for (int i = 0; i < 4; i++) {
            int f  = tid + i * 256;
            int r  = f >> 5;                 // 0..31
            int c4 = (f & 31) << 2;          // 0..124
            int gc = colBase + c4;
            float4 v = (gc + 3 < N) ? *reinterpret_cast<const float4*>(W + (size_t)(k0 + r) * N + gc) : z4;
            __nv_bfloat16 h, l;
            int o = r * SBN + c4;
            split_bf16(v.x, h, l); Bs_hi[o + 0] = h; Bs_lo[o + 0] = l;
            split_bf16(v.y, h, l); Bs_hi[o + 1] = h; Bs_lo[o + 1] = l;
            split_bf16(v.z, h, l); Bs_hi[o + 2] = h; Bs_lo[o + 2] = l;
            split_bf16(v.w, h, l); Bs_hi[o + 3] = h; Bs_lo[o + 3] = l;
        }
        __syncthreads();

#pragma unroll
        for (int kk = 0; kk < TBK / 16; kk++) {
            unsigned ah[4][4], al[4][4], bh[4][2], bl[4][2];
#pragma unroll
            for (int mf = 0; mf < 4; mf++) {
                int r = wm * 64 + mf * 16 + (lane & 15);
                int c = kk * 16 + ((lane >> 4) << 3);
                ldsm_x4(ah[mf], &As_hi[r * SAK + c]);
                ldsm_x4(al[mf], &As_lo[r * SAK + c]);
            }
#pragma unroll
            for (int nf = 0; nf < 4; nf++) {
                int r = kk * 16 + (lane & 15);
                int c = wn * 32 + nf * 8;
                ldsm_x2t(bh[nf], &Bs_hi[r * SBN + c]);
                ldsm_x2t(bl[nf], &Bs_lo[r * SBN + c]);
            }
#pragma unroll
            for (int mf = 0; mf < 4; mf++)
#pragma unroll
                for (int nf = 0; nf < 4; nf++) {
                    mma_bf16(acc[mf][nf], ah[mf], bh[nf]);
                    mma_bf16(acc[mf][nf], ah[mf], bl[nf]);
                    mma_bf16(acc[mf][nf], al[mf], bh[nf]);
                }
        }
        __syncthreads();
    }

    // ---- epilogue: bias, store, fused column stats ----
#pragma unroll
    for (int nf = 0; nf < 4; nf++) {
        int colb  = colBase + wn * 32 + nf * 8;
        bool colok = (colb < N);                 // N is a multiple of 8
        int coln  = colb + ((lane & 3) << 1);
        float b0 = (colok && bias) ? bias[coln]     : 0.f;
        float b1 = (colok && bias) ? bias[coln + 1] : 0.f;
        float s0 = 0.f, q0 = 0.f, s1 = 0.f, q1 = 0.f;
#pragma unroll
        for (int mf = 0; mf < 4; mf++) {
            int r0 = rowBase + wm * 64 + mf * 16 + (lane >> 2);
            float v0 = acc[mf][nf][0] + b0;
            float v1 = acc[mf][nf][1] + b1;
            float v2 = acc[mf][nf][2] + b0;
            float v3 = acc[mf][nf][3] + b1;
            if (colok && r0 < M) {
                *reinterpret_cast<float2*>(C + (size_t)r0 * N + coln) = make_float2(v0, v1);
                s0 += v0; q0 += v0 * v0; s1 += v1; q1 += v1 * v1;
            }
            if (colok && r0 + 8 < M) {
                *reinterpret_cast<float2*>(C + (size_t)(r0 + 8) * N + coln) = make_float2(v2, v3);
                s0 += v2; q0 += v2 * v2; s1 += v3; q1 += v3 * v3;
            }
        }
        if (do_stats && colok) {
#pragma unroll
            for (int o = 4; o < 32; o <<= 1) {
                s0 += __shfl_xor_sync(0xffffffffu, s0, o);
                q0 += __shfl_xor_sync(0xffffffffu, q0, o);
                s1 += __shfl_xor_sync(0xffffffffu, s1, o);
                q1 += __shfl_xor_sync(0xffffffffu, q1, o);
            }
            if (lane < 4) {
                atomicAdd(&g_stats[coln],         s0);
                atomicAdd(&g_stats[N + coln],     q0);
                atomicAdd(&g_stats[coln + 1],     s1);
                atomicAdd(&g_stats[N + coln + 1], q1);
            }
        }
    }
}

// ---------------- edge scatter (warp/edge, optional fused BN+ReLU on load) ------
__global__ void k_scatter(const float* __restrict__ h, float* agg, int F, int mode) {
    int w = (blockIdx.x * blockDim.x + threadIdx.x) >> 5;
    int lane = threadIdx.x & 31;
    if (w >= NE) return;
    int s = g_src[w];
    int d = g_dst[w];
    float norm = g_dinv[s] * g_dinv[d];
    const float4* hp = reinterpret_cast<const float4*>(h + (size_t)s * F);
    float* ap = agg + (size_t)d * F;
    int vecs = F >> 2;
    for (int v = lane; v < vecs; v += 32) {
        float4 x = hp[v];
        if (mode) {
            float4 sc = reinterpret_cast<const float4*>(g_scale)[v];
            float4 sh = reinterpret_cast<const float4*>(g_shift)[v];
            x.x = fmaxf(x.x * sc.x + sh.x, 0.f);
            x.y = fmaxf(x.y * sc.y + sh.y, 0.f);
            x.z = fmaxf(x.z * sc.z + sh.z, 0.f);
            x.w = fmaxf(x.w * sc.w + sh.w, 0.f);
        }
        x.x *= norm; x.y *= norm; x.z *= norm; x.w *= norm;
        asm volatile("red.global.add.v4.f32 [%0], {%1,%2,%3,%4};"
                     :: "l"(ap + (size_t)v * 4),
                        "f"(x.x), "f"(x.y), "f"(x.z), "f"(x.w)
                     : "memory");
    }
}

// ---------------- self-loop combine: p += f(xsrc) * dinv^2 ----------------------
__global__ void k_combine(float* p, const float* __restrict__ xsrc, int vshift, int mode) {
    long i  = (long)blockIdx.x * blockDim.x + threadIdx.x;
    long total = (long)NN << vshift;                 // rows * (F/4)
    long st = (long)gridDim.x * blockDim.x;
    int vmask = (1 << vshift) - 1;
    for (; i < total; i += st) {
        int row = (int)(i >> vshift);
        int v   = (int)(i & vmask);
        float di = g_dinv[row];
        float d2 = di * di;
        float4 x = reinterpret_cast<const float4*>(xsrc)[i];
        if (mode) {
            float4 sc = reinterpret_cast<const float4*>(g_scale)[v];
            float4 sh = reinterpret_cast<const float4*>(g_shift)[v];
            x.x = fmaxf(x.x * sc.x + sh.x, 0.f);
            x.y = fmaxf(x.y * sc.y + sh.y, 0.f);
            x.z = fmaxf(x.z * sc.z + sh.z, 0.f);
            x.w = fmaxf(x.w * sc.w + sh.w, 0.f);
        }
        float4 pv = reinterpret_cast<float4*>(p)[i];
        pv.x += x.x * d2; pv.y += x.y * d2; pv.z += x.z * d2; pv.w += x.w * d2;
        reinterpret_cast<float4*>(p)[i] = pv;
    }
}

// ---- layer-3: combine self-loop + bias (in place) and accumulate BN stats ------
__global__ void k_combine_stats(float* agg, const float* __restrict__ h,
                                const float* __restrict__ bias, int Nn, int F) {
    int c0 = threadIdx.x;
    bool a0 = c0 < F;
    float b0 = a0 ? bias[c0] : 0.f;
    float s0 = 0.f, q0 = 0.f;
    for (int r = blockIdx.x; r < Nn; r += gridDim.x) {
        float di = g_dinv[r];
        float d2 = di * di;
        size_t base = (size_t)r * F;
        if (a0) {
            float y = agg[base + c0] + h[base + c0] * d2 + b0;
            agg[base + c0] = y; s0 += y; q0 += y * y;
        }
    }
    if (a0) { atomicAdd(&g_stats[c0], s0); atomicAdd(&g_stats[F + c0], q0); }
}

__global__ void k_finalize(const float* __restrict__ g, const float* __restrict__ be,
                           int F, float invN) {
    int c = blockIdx.x * blockDim.x + threadIdx.x;
    if (c >= F) return;
    float mean = g_stats[c] * invN;
    float var  = g_stats[F + c] * invN - mean * mean;
    float sc = g[c] * rsqrtf(var + BN_EPS);
    g_scale[c] = sc;
    g_shift[c] = be[c] - mean * sc;
}

__global__ void k_apply(const float* __restrict__ y, float* __restrict__ o,
                        long n, int F, int relu) {
    long i  = ((long)blockIdx.x * blockDim.x + threadIdx.x) * 4;
    long st = (long)gridDim.x * blockDim.x * 4;
    for (; i < n; i += st) {
        float4 v = *reinterpret_cast<const float4*>(y + i);
        int c = (int)(i % F);
        v.x = v.x * g_scale[c]     + g_shift[c];
        v.y = v.y * g_scale[c + 1] + g_shift[c + 1];
        v.z = v.z * g_scale[c + 2] + g_shift[c + 2];
        v.w = v.w * g_scale[c + 3] + g_shift[c + 3];
        if (relu) {
            v.x = fmaxf(v.x, 0.f); v.y = fmaxf(v.y, 0.f);
            v.z = fmaxf(v.z, 0.f); v.w = fmaxf(v.w, 0.f);
        }
        *reinterpret_cast<float4*>(o + i) = v;
    }
}

// ---------------- host launch -----------------------------------------------
extern "C" void kernel_launch(void* const* d_in, const int* in_sizes, int n_in,
                              void* d_out, int out_size) {
    const float* x  = (const float*)d_in[0];
    const int*   ei = (const int*)d_in[1];
    const float *W1 = (const float*)d_in[2],  *b1 = (const float*)d_in[3];
    const float *g1 = (const float*)d_in[4],  *be1 = (const float*)d_in[5];
    const float *W2 = (const float*)d_in[6],  *b2 = (const float*)d_in[7];
    const float *g2 = (const float*)d_in[8],  *be2 = (const float*)d_in[9];
    const float *W3 = (const float*)d_in[10], *b3 = (const float*)d_in[11];
    const float *g3 = (const float*)d_in[12], *be3 = (const float*)d_in[13];

    float* out = (float*)d_out;                 // [NN, NCLS]
    float* x6  = out + (size_t)NN * NCLS;       // [NN, HID]

    void* p;
    cudaGetSymbolAddress(&p, g_bufA); float* bufA = (float*)p;  // y1 / y2
    cudaGetSymbolAddress(&p, g_bufB); float* bufB = (float*)p;  // px / p2
    cudaGetSymbolAddress(&p, g_h3);   float* h3   = (float*)p;
    cudaGetSymbolAddress(&p, g_ag3);  float* ag3  = (float*)p;
    cudaGetSymbolAddress(&p, g_deg);  int*   deg  = (int*)p;
    cudaGetSymbolAddress(&p, g_stats);float* st   = (float*)p;

    const long NF = (long)NN * FIN;
    const long NH = (long)NN * HID;
    const long NC = (long)NN * NCLS;
    const int  GZ = 4096;
    const int  SCAT_BLOCKS = NE / 8;            // 8 warps per block, warp/edge
    const float invN = 1.0f / (float)NN;
    const int  MB = (NN + TBM - 1) / TBM;       // 782

    // edge decode, degrees -> dinv
    k_detect <<<1, 256>>>(ei);
    k_convert<<<(NE + 255) / 256, 256>>>(ei);
    k_zero_i<<<(NN + 255) / 256, 256>>>(deg, NN);
    k_deg  <<<(NE + 255) / 256, 256>>>(NE);
    k_dinv <<<(NN + 255) / 256, 256>>>(NN);

    // -------- Layer 1 (aggregate first: p = Âx, then y1 = p@W1 + b1) --------
    k_zero_f4<<<GZ, 256>>>(bufB, NF);
    k_scatter<<<SCAT_BLOCKS, 256>>>(x, bufB, FIN, 0);
    k_combine<<<GZ, 256>>>(bufB, x, 5, 0);                       // F=128 -> vshift 5
    k_zero_f4<<<1, 256>>>(st, 2 * HID);
    k_gemm_tc<<<dim3(HID / TBN, MB), 256>>>(bufB, W1, b1, bufA, NN, HID, FIN, 1);
    k_finalize<<<2, 256>>>(g1, be1, HID, invN);

    // -------- Layer 2 (p2 = Â relu(bn(y1)), y2 = p2@W2 + b2) --------
    k_zero_f4<<<GZ, 256>>>(bufB, NH);
    k_scatter<<<SCAT_BLOCKS, 256>>>(bufA, bufB, HID, 1);         // fused BN+ReLU
    k_combine<<<GZ, 256>>>(bufB, bufA, 7, 1);                    // F=512 -> vshift 7
    k_zero_f4<<<1, 256>>>(st, 2 * HID);
    k_gemm_tc<<<dim3(HID / TBN, MB), 256>>>(bufB, W2, b2, bufA, NN, HID, HID, 1);
    k_finalize<<<2, 256>>>(g2, be2, HID, invN);
    k_apply<<<GZ, 256>>>(bufA, x6, NH, HID, 1);                  // x6 -> output

    // -------- Layer 3 (GEMM first: h3 = x6@W3, 40-wide scatter) --------
    k_gemm_tc<<<dim3(1, MB), 256>>>(x6, W3, (const float*)nullptr, h3, NN, NCLS, HID, 0);
    k_zero_f4<<<GZ, 256>>>(ag3, NC);
    k_scatter<<<SCAT_BLOCKS, 256>>>(h3, ag3, NCLS, 0);
    k_zero_f4<<<1, 256>>>(st, 2 * HID);
    k_combine_stats<<<2048, 64>>>(ag3, h3, b3, NN, NCLS);
    k_finalize<<<1, 64>>>(g3, be3, NCLS, invN);
    k_apply<<<GZ, 256>>>(ag3, out, NC, NCLS, 0);                 // out -> output
}

// round 13
// speedup vs baseline: 2.7656x; 1.2075x over previous
#include <cuda_runtime.h>
#include <cuda_bf16.h>

#define NN   100000
#define NE   800000
#define FIN  128
#define HID  512
#define NCLS 40
#define BN_EPS 1e-5f

// ---------------- scratch ----------------
__device__ __align__(16) float g_bufA[(size_t)NN * HID];   // y1 / y2
__device__ __align__(16) float g_bufB[(size_t)NN * HID];   // p1 / p2
__device__ __align__(16) float g_h3 [(size_t)NN * NCLS];
__device__ __align__(16) float g_ag3[(size_t)NN * NCLS];
__device__ int   g_src[NE];
__device__ int   g_dst[NE];
__device__ int   g_csrc[NE];       // CSR: src per slot (grouped by dst)
__device__ float g_cnorm[NE];      // CSR: dinv[s]*dinv[d] per slot
__device__ int   g_off[NN + 1];    // CSR offsets
__device__ int   g_cur[NN];        // fill cursors
__device__ int   g_is64;
__device__ int   g_deg[NN];
__device__ float g_dinv[NN];
__device__ float g_stats[2 * HID];
__device__ float g_scale[HID];
__device__ float g_shift[HID];

// ---------------- edge-index dtype probe + conversion ----------------
__global__ void k_detect(const int* __restrict__ raw) {
    __shared__ int nz;
    if (threadIdx.x == 0) nz = 0;
    __syncthreads();
    if (raw[threadIdx.x * 2 + 1] != 0) atomicAdd(&nz, 1);
    __syncthreads();
    if (threadIdx.x == 0) g_is64 = (nz == 0) ? 1 : 0;
}

__global__ void k_convert(const int* __restrict__ raw) {
    int i = blockIdx.x * blockDim.x + threadIdx.x;
    if (i >= NE) return;
    int s, d;
    if (g_is64) { s = raw[2 * i]; d = raw[2 * (NE + i)]; }
    else        { s = raw[i];     d = raw[NE + i]; }
    if ((unsigned)s >= NN) s = 0;
    if ((unsigned)d >= NN) d = 0;
    g_src[i] = s; g_dst[i] = d;
}

// ---------------- degree / dinv / CSR build ----------------
__global__ void k_zero_i(int* p, int n) {
    int i = blockIdx.x * blockDim.x + threadIdx.x;
    if (i < n) p[i] = 0;
}

__global__ void k_deg(int E) {
    int i = blockIdx.x * blockDim.x + threadIdx.x;
    if (i < E) atomicAdd(&g_deg[g_dst[i]], 1);
}

__global__ void k_dinv(int n) {
    int i = blockIdx.x * blockDim.x + threadIdx.x;
    if (i < n) g_dinv[i] = rsqrtf((float)g_deg[i] + 1.0f);
}

// single-block chunked exclusive scan of g_deg -> g_off (and copy to g_cur)
__global__ void k_scan() {
    __shared__ int sums[1024];
    const int t = threadIdx.x;
    const int CH = (NN + 1023) / 1024;
    int b = t * CH;
    int e = min(b + CH, NN);
    int s = 0;
    for (int i = b; i < e; i++) s += g_deg[i];
    sums[t] = s;
    __syncthreads();
    for (int o = 1; o < 1024; o <<= 1) {
        int v = (t >= o) ? sums[t - o] : 0;
        __syncthreads();
        sums[t] += v;
        __syncthreads();
    }
    int base = (t > 0) ? sums[t - 1] : 0;
    for (int i = b; i < e; i++) {
        g_off[i] = base;
        g_cur[i] = base;
        base += g_deg[i];
    }
    if (t == 1023) g_off[NN] = base;
}

__global__ void k_fill(int E) {
    int i = blockIdx.x * blockDim.x + threadIdx.x;
    if (i >= E) return;
    int s = g_src[i], d = g_dst[i];
    int pos = atomicAdd(&g_cur[d], 1);
    g_csrc[pos]  = s;
    g_cnorm[pos] = g_dinv[s] * g_dinv[d];
}

// ---------------- utility ----------------
__global__ void k_zero_f4(float* p, long n) {
    long i  = ((long)blockIdx.x * blockDim.x + threadIdx.x) * 4;
    long st = (long)gridDim.x * blockDim.x * 4;
    float4 z = make_float4(0.f, 0.f, 0.f, 0.f);
    for (; i < n; i += st) *reinterpret_cast<float4*>(p + i) = z;
}

// ---------------- bf16 split helpers ----------------
__device__ __forceinline__ void split_bf16(float x, __nv_bfloat16& h, __nv_bfloat16& l) {
    h = __float2bfloat16(x);
    l = __float2bfloat16(x - __bfloat162float(h));
}

__device__ __forceinline__ void ldsm_x4(unsigned* r, const void* p) {
    unsigned a = (unsigned)__cvta_generic_to_shared(p);
    asm volatile("ldmatrix.sync.aligned.m8n8.x4.shared.b16 {%0,%1,%2,%3}, [%4];"
                 : "=r"(r[0]), "=r"(r[1]), "=r"(r[2]), "=r"(r[3]) : "r"(a));
}
__device__ __forceinline__ void ldsm_x2t(unsigned* r, const void* p) {
    unsigned a = (unsigned)__cvta_generic_to_shared(p);
    asm volatile("ldmatrix.sync.aligned.m8n8.x2.trans.shared.b16 {%0,%1}, [%2];"
                 : "=r"(r[0]), "=r"(r[1]) : "r"(a));
}
__device__ __forceinline__ void mma_bf16(float* c, const unsigned* a, const unsigned* b) {
    asm volatile("mma.sync.aligned.m16n8k16.row.col.f32.bf16.bf16.f32 "
                 "{%0,%1,%2,%3}, {%4,%5,%6,%7}, {%8,%9}, {%0,%1,%2,%3};"
                 : "+f"(c[0]), "+f"(c[1]), "+f"(c[2]), "+f"(c[3])
                 : "r"(a[0]), "r"(a[1]), "r"(a[2]), "r"(a[3]),
                   "r"(b[0]), "r"(b[1]));
}

// ---------------- tensor-core GEMM (bf16 3-term split), C = A@W (+bias) ----------
#define TBM 128
#define TBN 128
#define TBK 32
#define SAK 40
#define SBN 136

__global__ __launch_bounds__(256, 1) void k_gemm_tc(
    const float* __restrict__ A, const float* __restrict__ W,
    const float* __restrict__ bias, float* __restrict__ C,
    int M, int N, int K, int do_stats)
{
    __shared__ __nv_bfloat16 As_hi[TBM * SAK], As_lo[TBM * SAK];
    __shared__ __nv_bfloat16 Bs_hi[TBK * SBN], Bs_lo[TBK * SBN];

    const int tid  = threadIdx.x;
    const int warp = tid >> 5, lane = tid & 31;
    const int wm = warp >> 2, wn = warp & 3;
    const int rowBase = blockIdx.y * TBM;
    const int colBase = blockIdx.x * TBN;

    float acc[4][4][4];
#pragma unroll
    for (int i = 0; i < 4; i++)
#pragma unroll
        for (int j = 0; j < 4; j++)
#pragma unroll
            for (int k = 0; k < 4; k++) acc[i][j][k] = 0.f;

    const float4 z4 = make_float4(0.f, 0.f, 0.f, 0.f);

    for (int k0 = 0; k0 < K; k0 += TBK) {
#pragma unroll
        for (int i = 0; i < 4; i++) {
            int f  = tid + i * 256;
            int r  = f >> 3;
            int c4 = (f & 7) << 2;
            int gr = rowBase + r;
            float4 v = (gr < M) ? *reinterpret_cast<const float4*>(A + (size_t)gr * K + k0 + c4) : z4;
            __nv_bfloat16 h, l;
            int o = r * SAK + c4;
            split_bf16(v.x, h, l); As_hi[o + 0] = h; As_lo[o + 0] = l;
            split_bf16(v.y, h, l); As_hi[o + 1] = h; As_lo[o + 1] = l;
            split_bf16(v.z, h, l); As_hi[o + 2] = h; As_lo[o + 2] = l;
            split_bf16(v.w, h, l); As_hi[o + 3] = h; As_lo[o + 3] = l;
        }
#pragma unroll
        for (int i = 0; i < 4; i++) {
            int f  = tid + i * 256;
            int r  = f >> 5;
            int c4 = (f & 31) << 2;
            int gc = colBase + c4;
            float4 v = (gc + 3 < N) ? *reinterpret_cast<const float4*>(W + (size_t)(k0 + r) * N + gc) : z4;
            __nv_bfloat16 h, l;
            int o = r * SBN + c4;
            split_bf16(v.x, h, l); Bs_hi[o + 0] = h; Bs_lo[o + 0] = l;
            split_bf16(v.y, h, l); Bs_hi[o + 1] = h; Bs_lo[o + 1] = l;
            split_bf16(v.z, h, l); Bs_hi[o + 2] = h; Bs_lo[o + 2] = l;
            split_bf16(v.w, h, l); Bs_hi[o + 3] = h; Bs_lo[o + 3] = l;
        }
        __syncthreads();

#pragma unroll
        for (int kk = 0; kk < TBK / 16; kk++) {
            unsigned ah[4][4], al[4][4], bh[4][2], bl[4][2];
#pragma unroll
            for (int mf = 0; mf < 4; mf++) {
                int r = wm * 64 + mf * 16 + (lane & 15);
                int c = kk * 16 + ((lane >> 4) << 3);
                ldsm_x4(ah[mf], &As_hi[r * SAK + c]);
                ldsm_x4(al[mf], &As_lo[r * SAK + c]);
            }
#pragma unroll
            for (int nf = 0; nf < 4; nf++) {
                int r = kk * 16 + (lane & 15);
                int c = wn * 32 + nf * 8;
                ldsm_x2t(bh[nf], &Bs_hi[r * SBN + c]);
                ldsm_x2t(bl[nf], &Bs_lo[r * SBN + c]);
            }
#pragma unroll
            for (int mf = 0; mf < 4; mf++)
#pragma unroll
                for (int nf = 0; nf < 4; nf++) {
                    mma_bf16(acc[mf][nf], ah[mf], bh[nf]);
                    mma_bf16(acc[mf][nf], ah[mf], bl[nf]);
                    mma_bf16(acc[mf][nf], al[mf], bh[nf]);
                }
        }
        __syncthreads();
    }

#pragma unroll
    for (int nf = 0; nf < 4; nf++) {
        int colb  = colBase + wn * 32 + nf * 8;
        bool colok = (colb < N);
        int coln  = colb + ((lane & 3) << 1);
        float b0 = (colok && bias) ? bias[coln]     : 0.f;
        float b1 = (colok && bias) ? bias[coln + 1] : 0.f;
        float s0 = 0.f, q0 = 0.f, s1 = 0.f, q1 = 0.f;
#pragma unroll
        for (int mf = 0; mf < 4; mf++) {
            int r0 = rowBase + wm * 64 + mf * 16 + (lane >> 2);
            float v0 = acc[mf][nf][0] + b0;
            float v1 = acc[mf][nf][1] + b1;
            float v2 = acc[mf][nf][2] + b0;
            float v3 = acc[mf][nf][3] + b1;
            if (colok && r0 < M) {
                *reinterpret_cast<float2*>(C + (size_t)r0 * N + coln) = make_float2(v0, v1);
                s0 += v0; q0 += v0 * v0; s1 += v1; q1 += v1 * v1;
            }
            if (colok && r0 + 8 < M) {
                *reinterpret_cast<float2*>(C + (size_t)(r0 + 8) * N + coln) = make_float2(v2, v3);
                s0 += v2; q0 += v2 * v2; s1 += v3; q1 += v3 * v3;
            }
        }
        if (do_stats && colok) {
#pragma unroll
            for (int o = 4; o < 32; o <<= 1) {
                s0 += __shfl_xor_sync(0xffffffffu, s0, o);
                q0 += __shfl_xor_sync(0xffffffffu, q0, o);
                s1 += __shfl_xor_sync(0xffffffffu, s1, o);
                q1 += __shfl_xor_sync(0xffffffffu, q1, o);
            }
            if (lane < 4) {
                atomicAdd(&g_stats[coln],         s0);
                atomicAdd(&g_stats[N + coln],     q0);
                atomicAdd(&g_stats[coln + 1],     s1);
                atomicAdd(&g_stats[N + coln + 1], q1);
            }
        }
    }
}

// ---------------- CSR gather: p[d] = sum norm*f(h[s]) + dinv^2 * f(h[d]) --------
// blockDim.x = F/4 (column float4 lanes), blockDim.y = nodes per block
__global__ void k_gather(const float* __restrict__ h, float* __restrict__ p,
                         int F, int mode) {
    int node = blockIdx.x * blockDim.y + threadIdx.y;
    if (node >= NN) return;
    int v = threadIdx.x;             // float4 column index
    float4 sc = make_float4(1.f, 1.f, 1.f, 1.f);
    float4 sh = make_float4(0.f, 0.f, 0.f, 0.f);
    if (mode) {
        sc = reinterpret_cast<const float4*>(g_scale)[v];
        sh = reinterpret_cast<const float4*>(g_shift)[v];
    }
    int beg = g_off[node], end = g_off[node + 1];
    float4 acc = make_float4(0.f, 0.f, 0.f, 0.f);
    for (int e = beg; e < end; e++) {
        int s = g_csrc[e];
        float nrm = g_cnorm[e];
        float4 x = reinterpret_cast<const float4*>(h + (size_t)s * F)[v];
        if (mode) {
            x.x = fmaxf(x.x * sc.x + sh.x, 0.f);
            x.y = fmaxf(x.y * sc.y + sh.y, 0.f);
            x.z = fmaxf(x.z * sc.z + sh.z, 0.f);
            x.w = fmaxf(x.w * sc.w + sh.w, 0.f);
        }
        acc.x += nrm * x.x; acc.y += nrm * x.y;
        acc.z += nrm * x.z; acc.w += nrm * x.w;
    }
    // self loop
    {
        float di = g_dinv[node];
        float d2 = di * di;
        float4 x = reinterpret_cast<const float4*>(h + (size_t)node * F)[v];
        if (mode) {
            x.x = fmaxf(x.x * sc.x + sh.x, 0.f);
            x.y = fmaxf(x.y * sc.y + sh.y, 0.f);
            x.z = fmaxf(x.z * sc.z + sh.z, 0.f);
            x.w = fmaxf(x.w * sc.w + sh.w, 0.f);
        }
        acc.x += d2 * x.x; acc.y += d2 * x.y;
        acc.z += d2 * x.z; acc.w += d2 * x.w;
    }
    reinterpret_cast<float4*>(p + (size_t)node * F)[v] = acc;
}

// ---------------- layer-3 gather (F=40): warp per node, bias fused -------------
__global__ void k_gather3(const float* __restrict__ h, float* __restrict__ y,
                          const float* __restrict__ bias) {
    int w = (blockIdx.x * blockDim.x + threadIdx.x) >> 5;
    int lane = threadIdx.x & 31;
    if (w >= NN || lane >= NCLS / 4) return;
    int v = lane;
    int beg = g_off[w], end = g_off[w + 1];
    float4 acc = make_float4(0.f, 0.f, 0.f, 0.f);
    for (int e = beg; e < end; e++) {
        int s = g_csrc[e];
        float nrm = g_cnorm[e];
        float4 x = reinterpret_cast<const float4*>(h + (size_t)s * NCLS)[v];
        acc.x += nrm * x.x; acc.y += nrm * x.y;
        acc.z += nrm * x.z; acc.w += nrm * x.w;
    }
    float di = g_dinv[w];
    float d2 = di * di;
    float4 x = reinterpret_cast<const float4*>(h + (size_t)w * NCLS)[v];
    float4 b = reinterpret_cast<const float4*>(bias)[v];
    acc.x += d2 * x.x + b.x; acc.y += d2 * x.y + b.y;
    acc.z += d2 * x.z + b.z; acc.w += d2 * x.w + b.w;
    reinterpret_cast<float4*>(y + (size_t)w * NCLS)[v] = acc;
}

// ---------------- column stats over an [NN, F] array ----------------------------
__global__ void k_stats(const float* __restrict__ y, int F) {
    int c = threadIdx.x;
    if (c >= F) return;
    float s = 0.f, q = 0.f;
    for (int r = blockIdx.x; r < NN; r += gridDim.x) {
        float v = y[(size_t)r * F + c];
        s += v; q += v * v;
    }
    atomicAdd(&g_stats[c], s);
    atomicAdd(&g_stats[F + c], q);
}

__global__ void k_finalize(const float* __restrict__ g, const float* __restrict__ be,
                           int F, float invN) {
    int c = blockIdx.x * blockDim.x + threadIdx.x;
    if (c >= F) return;
    float mean = g_stats[c] * invN;
    float var  = g_stats[F + c] * invN - mean * mean;
    float sc = g[c] * rsqrtf(var + BN_EPS);
    g_scale[c] = sc;
    g_shift[c] = be[c] - mean * sc;
}

__global__ void k_apply(const float* __restrict__ y, float* __restrict__ o,
                        long n, int F, int relu) {
    long i  = ((long)blockIdx.x * blockDim.x + threadIdx.x) * 4;
    long st = (long)gridDim.x * blockDim.x * 4;
    for (; i < n; i += st) {
        float4 v = *reinterpret_cast<const float4*>(y + i);
        int c = (int)(i % F);
        v.x = v.x * g_scale[c]     + g_shift[c];
        v.y = v.y * g_scale[c + 1] + g_shift[c + 1];
        v.z = v.z * g_scale[c + 2] + g_shift[c + 2];
        v.w = v.w * g_scale[c + 3] + g_shift[c + 3];
        if (relu) {
            v.x = fmaxf(v.x, 0.f); v.y = fmaxf(v.y, 0.f);
            v.z = fmaxf(v.z, 0.f); v.w = fmaxf(v.w, 0.f);
        }
        *reinterpret_cast<float4*>(o + i) = v;
    }
}

// ---------------- host launch -----------------------------------------------
extern "C" void kernel_launch(void* const* d_in, const int* in_sizes, int n_in,
                              void* d_out, int out_size) {
    const float* x  = (const float*)d_in[0];
    const int*   ei = (const int*)d_in[1];
    const float *W1 = (const float*)d_in[2],  *b1 = (const float*)d_in[3];
    const float *g1 = (const float*)d_in[4],  *be1 = (const float*)d_in[5];
    const float *W2 = (const float*)d_in[6],  *b2 = (const float*)d_in[7];
    const float *g2 = (const float*)d_in[8],  *be2 = (const float*)d_in[9];
    const float *W3 = (const float*)d_in[10], *b3 = (const float*)d_in[11];
    const float *g3 = (const float*)d_in[12], *be3 = (const float*)d_in[13];

    float* out = (float*)d_out;                 // [NN, NCLS]
    float* x6  = out + (size_t)NN * NCLS;       // [NN, HID]

    void* p;
    cudaGetSymbolAddress(&p, g_bufA); float* bufA = (float*)p;
    cudaGetSymbolAddress(&p, g_bufB); float* bufB = (float*)p;
    cudaGetSymbolAddress(&p, g_h3);   float* h3   = (float*)p;
    cudaGetSymbolAddress(&p, g_ag3);  float* ag3  = (float*)p;
    cudaGetSymbolAddress(&p, g_deg);  int*   deg  = (int*)p;
    cudaGetSymbolAddress(&p, g_stats);float* st   = (float*)p;

    const long NH = (long)NN * HID;
    const long NC = (long)NN * NCLS;
    const int  GZ = 4096;
    const float invN = 1.0f / (float)NN;
    const int  MB = (NN + TBM - 1) / TBM;

    // edge decode, degrees, dinv, CSR
    k_detect <<<1, 256>>>(ei);
    k_convert<<<(NE + 255) / 256, 256>>>(ei);
    k_zero_i <<<(NN + 255) / 256, 256>>>(deg, NN);
    k_deg    <<<(NE + 255) / 256, 256>>>(NE);
    k_dinv   <<<(NN + 255) / 256, 256>>>(NN);
    k_scan   <<<1, 1024>>>();
    k_fill   <<<(NE + 255) / 256, 256>>>(NE);

    dim3 gbl1(32, 8);   // F=128: 32 float4 lanes, 8 nodes/block
    dim3 gbl2(128, 2);  // F=512: 128 float4 lanes, 2 nodes/block

    // -------- Layer 1: p1 = Âx ; y1 = p1@W1 + b1 (stats fused) --------
    k_gather<<<(NN + 7) / 8, gbl1>>>(x, bufB, FIN, 0);
    k_zero_f4<<<1, 256>>>(st, 2 * HID);
    k_gemm_tc<<<dim3(HID / TBN, MB), 256>>>(bufB, W1, b1, bufA, NN, HID, FIN, 1);
    k_finalize<<<2, 256>>>(g1, be1, HID, invN);

    // -------- Layer 2: p2 = Â relu(bn(y1)) ; y2 = p2@W2 + b2 --------
    k_gather<<<(NN + 1) / 2, gbl2>>>(bufA, bufB, HID, 1);
    k_zero_f4<<<1, 256>>>(st, 2 * HID);
    k_gemm_tc<<<dim3(HID / TBN, MB), 256>>>(bufB, W2, b2, bufA, NN, HID, HID, 1);
    k_finalize<<<2, 256>>>(g2, be2, HID, invN);
    k_apply<<<GZ, 256>>>(bufA, x6, NH, HID, 1);          // x6 -> output

    // -------- Layer 3: h3 = x6@W3 ; y3 = Âh3 + b3 ; bn --------
    k_gemm_tc<<<dim3(1, MB), 256>>>(x6, W3, (const float*)nullptr, h3, NN, NCLS, HID, 0);
    k_gather3<<<(NN * 32 + 255) / 256, 256>>>(h3, ag3, b3);
    k_zero_f4<<<1, 256>>>(st, 2 * HID);
    k_stats<<<2048, 64>>>(ag3, NCLS);
    k_finalize<<<1, 64>>>(g3, be3, NCLS, invN);
    k_apply<<<GZ, 256>>>(ag3, out, NC, NCLS, 0);         // out -> output
}

// round 17
// speedup vs baseline: 3.4597x; 1.2510x over previous
#include <cuda_runtime.h>
#include <cuda_bf16.h>

#define NN   100000
#define NE   800000
#define FIN  128
#define HID  512
#define NCLS 40
#define BN_EPS 1e-5f

// ---------------- scratch ----------------
__device__ __align__(16) float g_bufA[(size_t)NN * HID];            // y1 / y2 (fp32)
__device__ __align__(16) __nv_bfloat16 g_Ahi[(size_t)NN * HID];     // GEMM A operand (hi)
__device__ __align__(16) __nv_bfloat16 g_Alo[(size_t)NN * HID];     // GEMM A operand (lo)
__device__ __align__(16) __nv_bfloat16 g_W1hi[FIN * HID], g_W1lo[FIN * HID];
__device__ __align__(16) __nv_bfloat16 g_W2hi[HID * HID], g_W2lo[HID * HID];
__device__ __align__(16) __nv_bfloat16 g_W3hi[HID * 128], g_W3lo[HID * 128];  // N padded 40->128
__device__ __align__(16) float g_h3 [(size_t)NN * NCLS];
__device__ __align__(16) float g_ag3[(size_t)NN * NCLS];
__device__ int   g_src[NE];
__device__ int   g_dst[NE];
__device__ int   g_csrc[NE];
__device__ float g_cnorm[NE];
__device__ int   g_off[NN + 1];
__device__ int   g_cur[NN];
__device__ int   g_is64;
__device__ int   g_deg[NN];
__device__ float g_dinv[NN];
__device__ float g_stats[2 * HID];
__device__ float g_scale[HID];
__device__ float g_shift[HID];

// ---------------- edge-index dtype probe + conversion ----------------
__global__ void k_detect(const int* __restrict__ raw) {
    __shared__ int nz;
    if (threadIdx.x == 0) nz = 0;
    __syncthreads();
    if (raw[threadIdx.x * 2 + 1] != 0) atomicAdd(&nz, 1);
    __syncthreads();
    if (threadIdx.x == 0) g_is64 = (nz == 0) ? 1 : 0;
}

__global__ void k_convert(const int* __restrict__ raw) {
    int i = blockIdx.x * blockDim.x + threadIdx.x;
    if (i >= NE) return;
    int s, d;
    if (g_is64) { s = raw[2 * i]; d = raw[2 * (NE + i)]; }
    else        { s = raw[i];     d = raw[NE + i]; }
    if ((unsigned)s >= NN) s = 0;
    if ((unsigned)d >= NN) d = 0;
    g_src[i] = s; g_dst[i] = d;
}

// ---------------- degree / dinv / CSR build ----------------
__global__ void k_zero_i(int* p, int n) {
    int i = blockIdx.x * blockDim.x + threadIdx.x;
    if (i < n) p[i] = 0;
}

__global__ void k_deg(int E) {
    int i = blockIdx.x * blockDim.x + threadIdx.x;
    if (i < E) atomicAdd(&g_deg[g_dst[i]], 1);
}

__global__ void k_dinv(int n) {
    int i = blockIdx.x * blockDim.x + threadIdx.x;
    if (i < n) g_dinv[i] = rsqrtf((float)g_deg[i] + 1.0f);
}

__global__ void k_scan() {
    __shared__ int sums[1024];
    const int t = threadIdx.x;
    const int CH = (NN + 1023) / 1024;
    int b = t * CH;
    int e = min(b + CH, NN);
    int s = 0;
    for (int i = b; i < e; i++) s += g_deg[i];
    sums[t] = s;
    __syncthreads();
    for (int o = 1; o < 1024; o <<= 1) {
        int v = (t >= o) ? sums[t - o] : 0;
        __syncthreads();
        sums[t] += v;
        __syncthreads();
    }
    int base = (t > 0) ? sums[t - 1] : 0;
    for (int i = b; i < e; i++) {
        g_off[i] = base;
        g_cur[i] = base;
        base += g_deg[i];
    }
    if (t == 1023) g_off[NN] = base;
}

__global__ void k_fill(int E) {
    int i = blockIdx.x * blockDim.x + threadIdx.x;
    if (i >= E) return;
    int s = g_src[i], d = g_dst[i];
    int pos = atomicAdd(&g_cur[d], 1);
    g_csrc[pos]  = s;
    g_cnorm[pos] = g_dinv[s] * g_dinv[d];
}

// ---------------- utility ----------------
__global__ void k_zero_f4(float* p, long n) {
    long i  = ((long)blockIdx.x * blockDim.x + threadIdx.x) * 4;
    long st = (long)gridDim.x * blockDim.x * 4;
    float4 z = make_float4(0.f, 0.f, 0.f, 0.f);
    for (; i < n; i += st) *reinterpret_cast<float4*>(p + i) = z;
}

// ---------------- bf16 helpers ----------------
__device__ __forceinline__ void split_bf16(float x, __nv_bfloat16& h, __nv_bfloat16& l) {
    h = __float2bfloat16(x);
    l = __float2bfloat16(x - __bfloat162float(h));
}

__device__ __forceinline__ void store_split4(__nv_bfloat16* hi, __nv_bfloat16* lo,
                                             size_t idx, float4 a) {
    __nv_bfloat16 hv[4], lv[4];
    split_bf16(a.x, hv[0], lv[0]);
    split_bf16(a.y, hv[1], lv[1]);
    split_bf16(a.z, hv[2], lv[2]);
    split_bf16(a.w, hv[3], lv[3]);
    *reinterpret_cast<uint2*>(hi + idx) = *reinterpret_cast<uint2*>(hv);
    *reinterpret_cast<uint2*>(lo + idx) = *reinterpret_cast<uint2*>(lv);
}

__device__ __forceinline__ void ldsm_x4(unsigned* r, const void* p) {
    unsigned a = (unsigned)__cvta_generic_to_shared(p);
    asm volatile("ldmatrix.sync.aligned.m8n8.x4.shared.b16 {%0,%1,%2,%3}, [%4];"
                 : "=r"(r[0]), "=r"(r[1]), "=r"(r[2]), "=r"(r[3]) : "r"(a));
}
__device__ __forceinline__ void ldsm_x2t(unsigned* r, const void* p) {
    unsigned a = (unsigned)__cvta_generic_to_shared(p);
    asm volatile("ldmatrix.sync.aligned.m8n8.x2.trans.shared.b16 {%0,%1}, [%2];"
                 : "=r"(r[0]), "=r"(r[1]) : "r"(a));
}
__device__ __forceinline__ void mma_bf16(float* c, const unsigned* a, const unsigned* b) {
    asm volatile("mma.sync.aligned.m16n8k16.row.col.f32.bf16.bf16.f32 "
                 "{%0,%1,%2,%3}, {%4,%5,%6,%7}, {%8,%9}, {%0,%1,%2,%3};"
                 : "+f"(c[0]), "+f"(c[1]), "+f"(c[2]), "+f"(c[3])
                 : "r"(a[0]), "r"(a[1]), "r"(a[2]), "r"(a[3]),
                   "r"(b[0]), "r"(b[1]));
}

__device__ __forceinline__ void cp16(void* s, const void* g) {
    unsigned a = (unsigned)__cvta_generic_to_shared(s);
    asm volatile("cp.async.cg.shared.global [%0], [%1], 16;" :: "r"(a), "l"(g));
}

// ---------------- weight pre-split (fp32 -> bf16 hi/lo, optional column pad) ----
__global__ void k_splitW(const float* __restrict__ W, __nv_bfloat16* __restrict__ hi,
                         __nv_bfloat16* __restrict__ lo, int K, int N, int Npad) {
    int i = blockIdx.x * blockDim.x + threadIdx.x;
    if (i >= K * Npad) return;
    int r = i / Npad, c = i - r * Npad;
    float v = (c < N) ? W[(size_t)r * N + c] : 0.f;
    __nv_bfloat16 h, l;
    split_bf16(v, h, l);
    hi[i] = h; lo[i] = l;
}

// ------------- tensor-core GEMM, pre-split bf16 operands, cp.async 2-stage ------
#define TBM 128
#define TBN 128
#define TBK 32
#define SAK 40
#define SBN 136
#define A_ELEMS (TBM * SAK)            // 5120
#define B_ELEMS (TBK * SBN)            // 4352
#define STAGE_ELEMS (2 * A_ELEMS + 2 * B_ELEMS)   // 18944
#define GEMM_SMEM (2 * STAGE_ELEMS * 2)           // bytes = 75776

__global__ __launch_bounds__(256, 1) void k_gemm_tc(
    const __nv_bfloat16* __restrict__ Ahi, const __nv_bfloat16* __restrict__ Alo,
    const __nv_bfloat16* __restrict__ Bhi, const __nv_bfloat16* __restrict__ Blo,
    const float* __restrict__ bias, float* __restrict__ C,
    int M, int N, int K, int ldb, int do_stats)
{
    extern __shared__ __nv_bfloat16 smem[];

    const int tid  = threadIdx.x;
    const int warp = tid >> 5, lane = tid & 31;
    const int wm = warp >> 2, wn = warp & 3;
    const int rowBase = blockIdx.y * TBM;
    const int colBase = blockIdx.x * TBN;

    float acc[4][4][4];
#pragma unroll
    for (int i = 0; i < 4; i++)
#pragma unroll
        for (int j = 0; j < 4; j++)
#pragma unroll
            for (int k = 0; k < 4; k++) acc[i][j][k] = 0.f;

    auto loadtile = [&](int st, int k0) {
        __nv_bfloat16* As_h = smem + st * STAGE_ELEMS;
        __nv_bfloat16* As_l = As_h + A_ELEMS;
        __nv_bfloat16* Bs_h = As_l + A_ELEMS;
        __nv_bfloat16* Bs_l = Bs_h + B_ELEMS;
#pragma unroll
        for (int i = 0; i < 2; i++) {
            int c  = tid + i * 256;          // 0..511
            int r  = c >> 2;                 // 0..127
            int co = (c & 3) << 3;           // 0,8,16,24
            int gr = rowBase + r;
            if (gr > M - 1) gr = M - 1;      // clamp: OOB rows computed, never stored
            size_t go = (size_t)gr * K + k0 + co;
            cp16(As_h + r * SAK + co, Ahi + go);
            cp16(As_l + r * SAK + co, Alo + go);
        }
#pragma unroll
        for (int i = 0; i < 2; i++) {
            int c  = tid + i * 256;
            int r  = c >> 4;                 // 0..31
            int co = (c & 15) << 3;          // 0..120
            size_t go = (size_t)(k0 + r) * ldb + colBase + co;
            cp16(Bs_h + r * SBN + co, Bhi + go);
            cp16(Bs_l + r * SBN + co, Blo + go);
        }
    };

    const int KT = K / TBK;
    loadtile(0, 0);
    asm volatile("cp.async.commit_group;");

    for (int kt = 0; kt < KT; kt++) {
        int st = kt & 1;
        if (kt + 1 < KT) {
            loadtile(st ^ 1, (kt + 1) * TBK);
            asm volatile("cp.async.commit_group;");
            asm volatile("cp.async.wait_group 1;");
        } else {
            asm volatile("cp.async.wait_group 0;");
        }
        __syncthreads();

        const __nv_bfloat16* As_h = smem + st * STAGE_ELEMS;
        const __nv_bfloat16* As_l = As_h + A_ELEMS;
        const __nv_bfloat16* Bs_h = As_l + A_ELEMS;
        const __nv_bfloat16* Bs_l = Bs_h + B_ELEMS;

#pragma unroll
        for (int kk = 0; kk < TBK / 16; kk++) {
            unsigned ah[4][4], al[4][4], bh[4][2], bl[4][2];
#pragma unroll
            for (int mf = 0; mf < 4; mf++) {
                int r = wm * 64 + mf * 16 + (lane & 15);
                int c = kk * 16 + ((lane >> 4) << 3);
                ldsm_x4(ah[mf], &As_h[r * SAK + c]);
                ldsm_x4(al[mf], &As_l[r * SAK + c]);
            }
#pragma unroll
            for (int nf = 0; nf < 4; nf++) {
                int r = kk * 16 + (lane & 15);
                int c = wn * 32 + nf * 8;
                ldsm_x2t(bh[nf], &Bs_h[r * SBN + c]);
                ldsm_x2t(bl[nf], &Bs_l[r * SBN + c]);
            }
#pragma unroll
            for (int mf = 0; mf < 4; mf++)
#pragma unroll
                for (int nf = 0; nf < 4; nf++) {
                    mma_bf16(acc[mf][nf], ah[mf], bh[nf]);
                    mma_bf16(acc[mf][nf], ah[mf], bl[nf]);
                    mma_bf16(acc[mf][nf], al[mf], bh[nf]);
                }
        }
        __syncthreads();
    }

    // ---- epilogue: bias, store, fused column stats ----
#pragma unroll
    for (int nf = 0; nf < 4; nf++) {
        int colb  = colBase + wn * 32 + nf * 8;
        bool colok = (colb < N);
        int coln  = colb + ((lane & 3) << 1);
        float b0 = (colok && bias) ? bias[coln]     : 0.f;
        float b1 = (colok && bias) ? bias[coln + 1] : 0.f;
        float s0 = 0.f, q0 = 0.f, s1 = 0.f, q1 = 0.f;
#pragma unroll
        for (int mf = 0; mf < 4; mf++) {
            int r0 = rowBase + wm * 64 + mf * 16 + (lane >> 2);
            float v0 = acc[mf][nf][0] + b0;
            float v1 = acc[mf][nf][1] + b1;
            float v2 = acc[mf][nf][2] + b0;
            float v3 = acc[mf][nf][3] + b1;
            if (colok && r0 < M) {
                *reinterpret_cast<float2*>(C + (size_t)r0 * N + coln) = make_float2(v0, v1);
                s0 += v0; q0 += v0 * v0; s1 += v1; q1 += v1 * v1;
            }
            if (colok && r0 + 8 < M) {
                *reinterpret_cast<float2*>(C + (size_t)(r0 + 8) * N + coln) = make_float2(v2, v3);
                s0 += v2; q0 += v2 * v2; s1 += v3; q1 += v3 * v3;
            }
        }
        if (do_stats && colok) {
#pragma unroll
            for (int o = 4; o < 32; o <<= 1) {
                s0 += __shfl_xor_sync(0xffffffffu, s0, o);
                q0 += __shfl_xor_sync(0xffffffffu, q0, o);
                s1 += __shfl_xor_sync(0xffffffffu, s1, o);
                q1 += __shfl_xor_sync(0xffffffffu, q1, o);
            }
            if (lane < 4) {
                atomicAdd(&g_stats[coln],         s0);
                atomicAdd(&g_stats[N + coln],     q0);
                atomicAdd(&g_stats[coln + 1],     s1);
                atomicAdd(&g_stats[N + coln + 1], q1);
            }
        }
    }
}

// ---------------- CSR gather: writes split bf16 operand directly -----------------
__global__ void k_gather(const float* __restrict__ h,
                         __nv_bfloat16* __restrict__ phi, __nv_bfloat16* __restrict__ plo,
                         int F, int mode) {
    int node = blockIdx.x * blockDim.y + threadIdx.y;
    if (node >= NN) return;
    int v = threadIdx.x;
    float4 sc = make_float4(1.f, 1.f, 1.f, 1.f);
    float4 sh = make_float4(0.f, 0.f, 0.f, 0.f);
    if (mode) {
        sc = reinterpret_cast<const float4*>(g_scale)[v];
        sh = reinterpret_cast<const float4*>(g_shift)[v];
    }
    int beg = g_off[node], end = g_off[node + 1];
    float4 acc = make_float4(0.f, 0.f, 0.f, 0.f);
    for (int e = beg; e < end; e++) {
        int s = g_csrc[e];
        float nrm = g_cnorm[e];
        float4 x = reinterpret_cast<const float4*>(h + (size_t)s * F)[v];
        if (mode) {
            x.x = fmaxf(x.x * sc.x + sh.x, 0.f);
            x.y = fmaxf(x.y * sc.y + sh.y, 0.f);
            x.z = fmaxf(x.z * sc.z + sh.z, 0.f);
            x.w = fmaxf(x.w * sc.w + sh.w, 0.f);
        }
        acc.x += nrm * x.x; acc.y += nrm * x.y;
        acc.z += nrm * x.z; acc.w += nrm * x.w;
    }
    {
        float di = g_dinv[node];
        float d2 = di * di;
        float4 x = reinterpret_cast<const float4*>(h + (size_t)node * F)[v];
        if (mode) {
            x.x = fmaxf(x.x * sc.x + sh.x, 0.f);
            x.y = fmaxf(x.y * sc.y + sh.y, 0.f);
            x.z = fmaxf(x.z * sc.z + sh.z, 0.f);
            x.w = fmaxf(x.w * sc.w + sh.w, 0.f);
        }
        acc.x += d2 * x.x; acc.y += d2 * x.y;
        acc.z += d2 * x.z; acc.w += d2 * x.w;
    }
    store_split4(phi, plo, (size_t)node * F + v * 4, acc);
}

// ---------------- layer-3 gather (F=40): warp per node, bias fused -------------
__global__ void k_gather3(const float* __restrict__ h, float* __restrict__ y,
                          const float* __restrict__ bias) {
    int w = (blockIdx.x * blockDim.x + threadIdx.x) >> 5;
    int lane = threadIdx.x & 31;
    if (w >= NN || lane >= NCLS / 4) return;
    int v = lane;
    int beg = g_off[w], end = g_off[w + 1];
    float4 acc = make_float4(0.f, 0.f, 0.f, 0.f);
    for (int e = beg; e < end; e++) {
        int s = g_csrc[e];
        float nrm = g_cnorm[e];
        float4 x = reinterpret_cast<const float4*>(h + (size_t)s * NCLS)[v];
        acc.x += nrm * x.x; acc.y += nrm * x.y;
        acc.z += nrm * x.z; acc.w += nrm * x.w;
    }
    float di = g_dinv[w];
    float d2 = di * di;
    float4 x = reinterpret_cast<const float4*>(h + (size_t)w * NCLS)[v];
    float4 b = reinterpret_cast<const float4*>(bias)[v];
    acc.x += d2 * x.x + b.x; acc.y += d2 * x.y + b.y;
    acc.z += d2 * x.z + b.z; acc.w += d2 * x.w + b.w;
    reinterpret_cast<float4*>(y + (size_t)w * NCLS)[v] = acc;
}

// ---------------- column stats over an [NN, F] array ----------------------------
__global__ void k_stats(const float* __restrict__ y, int F) {
    int c = threadIdx.x;
    if (c >= F) return;
    float s = 0.f, q = 0.f;
    for (int r = blockIdx.x; r < NN; r += gridDim.x) {
        float v = y[(size_t)r * F + c];
        s += v; q += v * v;
    }
    atomicAdd(&g_stats[c], s);
    atomicAdd(&g_stats[F + c], q);
}

__global__ void k_finalize(const float* __restrict__ g, const float* __restrict__ be,
                           int F, float invN) {
    int c = blockIdx.x * blockDim.x + threadIdx.x;
    if (c >= F) return;
    float mean = g_stats[c] * invN;
    float var  = g_stats[F + c] * invN - mean * mean;
    float sc = g[c] * rsqrtf(var + BN_EPS);
    g_scale[c] = sc;
    g_shift[c] = be[c] - mean * sc;
}

// BN apply (+optional ReLU); optionally also emits split bf16 copy for next GEMM
__global__ void k_apply(const float* __restrict__ y, float* __restrict__ o,
                        __nv_bfloat16* hi, __nv_bfloat16* lo,
                        long n, int F, int relu) {
    long i  = ((long)blockIdx.x * blockDim.x + threadIdx.x) * 4;
    long st = (long)gridDim.x * blockDim.x * 4;
    for (; i < n; i += st) {
        float4 v = *reinterpret_cast<const float4*>(y + i);
        int c = (int)(i % F);
        v.x = v.x * g_scale[c]     + g_shift[c];
        v.y = v.y * g_scale[c + 1] + g_shift[c + 1];
        v.z = v.z * g_scale[c + 2] + g_shift[c + 2];
        v.w = v.w * g_scale[c + 3] + g_shift[c + 3];
        if (relu) {
            v.x = fmaxf(v.x, 0.f); v.y = fmaxf(v.y, 0.f);
            v.z = fmaxf(v.z, 0.f); v.w = fmaxf(v.w, 0.f);
        }
        *reinterpret_cast<float4*>(o + i) = v;
        if (hi) store_split4(hi, lo, i, v);
    }
}

// ---------------- host launch -----------------------------------------------
extern "C" void kernel_launch(void* const* d_in, const int* in_sizes, int n_in,
                              void* d_out, int out_size) {
    const float* x  = (const float*)d_in[0];
    const int*   ei = (const int*)d_in[1];
    const float *W1 = (const float*)d_in[2],  *b1 = (const float*)d_in[3];
    const float *g1 = (const float*)d_in[4],  *be1 = (const float*)d_in[5];
    const float *W2 = (const float*)d_in[6],  *b2 = (const float*)d_in[7];
    const float *g2 = (const float*)d_in[8],  *be2 = (const float*)d_in[9];
    const float *W3 = (const float*)d_in[10], *b3 = (const float*)d_in[11];
    const float *g3 = (const float*)d_in[12], *be3 = (const float*)d_in[13];

    float* out = (float*)d_out;                 // [NN, NCLS]
    float* x6  = out + (size_t)NN * NCLS;       // [NN, HID]

    void* p;
    cudaGetSymbolAddress(&p, g_bufA); float* bufA = (float*)p;
    cudaGetSymbolAddress(&p, g_Ahi);  __nv_bfloat16* Ahi = (__nv_bfloat16*)p;
    cudaGetSymbolAddress(&p, g_Alo);  __nv_bfloat16* Alo = (__nv_bfloat16*)p;
    cudaGetSymbolAddress(&p, g_W1hi); __nv_bfloat16* W1h = (__nv_bfloat16*)p;
    cudaGetSymbolAddress(&p, g_W1lo); __nv_bfloat16* W1l = (__nv_bfloat16*)p;
    cudaGetSymbolAddress(&p, g_W2hi); __nv_bfloat16* W2h = (__nv_bfloat16*)p;
    cudaGetSymbolAddress(&p, g_W2lo); __nv_bfloat16* W2l = (__nv_bfloat16*)p;
    cudaGetSymbolAddress(&p, g_W3hi); __nv_bfloat16* W3h = (__nv_bfloat16*)p;
    cudaGetSymbolAddress(&p, g_W3lo); __nv_bfloat16* W3l = (__nv_bfloat16*)p;
    cudaGetSymbolAddress(&p, g_h3);   float* h3   = (float*)p;
    cudaGetSymbolAddress(&p, g_ag3);  float* ag3  = (float*)p;
    cudaGetSymbolAddress(&p, g_deg);  int*   deg  = (int*)p;
    cudaGetSymbolAddress(&p, g_stats);float* st   = (float*)p;

    static int smem_set = 0;
    if (!smem_set) {
        cudaFuncSetAttribute(k_gemm_tc, cudaFuncAttributeMaxDynamicSharedMemorySize, GEMM_SMEM);
        smem_set = 1;
    }

    const long NH = (long)NN * HID;
    const long NC = (long)NN * NCLS;
    const int  GZ = 4096;
    const float invN = 1.0f / (float)NN;
    const int  MB = (NN + TBM - 1) / TBM;

    // edge decode, degrees, dinv, CSR, weight pre-split
    k_detect <<<1, 256>>>(ei);
    k_convert<<<(NE + 255) / 256, 256>>>(ei);
    k_zero_i <<<(NN + 255) / 256, 256>>>(deg, NN);
    k_deg    <<<(NE + 255) / 256, 256>>>(NE);
    k_dinv   <<<(NN + 255) / 256, 256>>>(NN);
    k_scan   <<<1, 1024>>>();
    k_fill   <<<(NE + 255) / 256, 256>>>(NE);
    k_splitW <<<(FIN * HID + 255) / 256, 256>>>(W1, W1h, W1l, FIN, HID, HID);
    k_splitW <<<(HID * HID + 255) / 256, 256>>>(W2, W2h, W2l, HID, HID, HID);
    k_splitW <<<(HID * 128 + 255) / 256, 256>>>(W3, W3h, W3l, HID, NCLS, 128);

    dim3 gbl1(32, 8);   // F=128
    dim3 gbl2(128, 2);  // F=512

    // -------- Layer 1: p1 = Âx (split) ; y1 = p1@W1 + b1 (stats fused) --------
    k_gather<<<(NN + 7) / 8, gbl1>>>(x, Ahi, Alo, FIN, 0);
    k_zero_f4<<<1, 256>>>(st, 2 * HID);
    k_gemm_tc<<<dim3(HID / TBN, MB), 256, GEMM_SMEM>>>(Ahi, Alo, W1h, W1l, b1, bufA,
                                                       NN, HID, FIN, HID, 1);
    k_finalize<<<2, 256>>>(g1, be1, HID, invN);

    // -------- Layer 2: p2 = Â relu(bn(y1)) (split) ; y2 = p2@W2 + b2 --------
    k_gather<<<(NN + 1) / 2, gbl2>>>(bufA, Ahi, Alo, HID, 1);
    k_zero_f4<<<1, 256>>>(st, 2 * HID);
    k_gemm_tc<<<dim3(HID / TBN, MB), 256, GEMM_SMEM>>>(Ahi, Alo, W2h, W2l, b2, bufA,
                                                       NN, HID, HID, HID, 1);
    k_finalize<<<2, 256>>>(g2, be2, HID, invN);
    k_apply<<<GZ, 256>>>(bufA, x6, Ahi, Alo, NH, HID, 1);   // x6 + split for GEMM3

    // -------- Layer 3: h3 = x6@W3 ; y3 = Âh3 + b3 ; bn --------
    k_gemm_tc<<<dim3(1, MB), 256, GEMM_SMEM>>>(Ahi, Alo, W3h, W3l,
                                               (const float*)nullptr, h3,
                                               NN, NCLS, HID, 128, 0);
    k_gather3<<<(NN * 32 + 255) / 256, 256>>>(h3, ag3, b3);
    k_zero_f4<<<1, 256>>>(st, 2 * HID);
    k_stats<<<2048, 64>>>(ag3, NCLS);
    k_finalize<<<1, 64>>>(g3, be3, NCLS, invN);
    k_apply<<<GZ, 256>>>(ag3, out, (__nv_bfloat16*)nullptr, (__nv_bfloat16*)nullptr,
                         NC, NCLS, 0);
}